// round 7
// baseline (speedup 1.0000x reference)
#include <cuda_runtime.h>
#include <cuda_bf16.h>
#include <cstdint>
#include <cstddef>

// ============================================================================
// QUIK quantized linear, B = in = out = 4096.
//   x_q = trunc(clip((x - min(x))/((max-min)/8) - 4, -4, 3))   (global affine)
//   w_q likewise; out[i,j] = (x_q[i,:]·w_q[j,:] + bias[j])*s_a*s_w
//                            + (zero_a + 4*s_a)*rowsum_w[i]    (note index i)
// Quantized values are int8-exact -> s8 IMMA (mma.sync, plain sm_103-legal)
// with s32 accumulation is bit-exact for the integer GEMM.
// ============================================================================

#define DIM 4096
#define BM 128
#define BN 128
#define BK 128            // int8 elements per k-tile = 128 bytes per row
#define NITER (DIM / BK)  // 32
#define STAGES 3
#define STAGE_BYTES (2 * BM * BK)          // A(16K) + B(16K) = 32768
#define SMEM_TOTAL (STAGES * STAGE_BYTES)  // 98304

// ---------------- device scratch (allocation-free rule) ---------------------
__device__ unsigned g_xmin_e, g_xmax_e, g_wmin_e, g_wmax_e;
__device__ float g_rowsum[DIM];
__device__ float g_consts[8];  // 0:s=sa*sw 1:shiftc 2:x_zero 3:x_scale 4:w_zero 5:w_scale
__device__ int8_t g_xq8[(size_t)DIM * DIM];
__device__ int8_t g_wq8[(size_t)DIM * DIM];

// ---------------- PTX helpers (all plain-sm80/75 features) ------------------
__device__ __forceinline__ uint32_t smem_to_u32(const void* p) {
    uint32_t a;
    asm("{ .reg .u64 t; cvta.to.shared.u64 t, %1; cvt.u32.u64 %0, t; }" : "=r"(a) : "l"(p));
    return a;
}

#define CP_ASYNC16(saddr, gptr)                                              \
    asm volatile("cp.async.cg.shared.global [%0], [%1], 16;"                 \
                 :: "r"(saddr), "l"(gptr) : "memory")
#define CP_COMMIT() asm volatile("cp.async.commit_group;" ::: "memory")
#define CP_WAIT1()  asm volatile("cp.async.wait_group 1;" ::: "memory")

#define LDSM_X4(r, addr)                                                     \
    asm volatile("ldmatrix.sync.aligned.m8n8.x4.shared.b16 {%0,%1,%2,%3}, [%4];" \
                 : "=r"((r)[0]), "=r"((r)[1]), "=r"((r)[2]), "=r"((r)[3])    \
                 : "r"(addr))

#define MMA_S8(c, a, b0v, b1v)                                               \
    asm volatile("mma.sync.aligned.m16n8k32.row.col.s32.s8.s8.s32 "          \
                 "{%0,%1,%2,%3}, {%4,%5,%6,%7}, {%8,%9}, {%0,%1,%2,%3};"     \
                 : "+r"((c)[0]), "+r"((c)[1]), "+r"((c)[2]), "+r"((c)[3])    \
                 : "r"((a)[0]), "r"((a)[1]), "r"((a)[2]), "r"((a)[3]),       \
                   "r"(b0v), "r"(b1v))

// Monotone float<->uint encoding for atomic min/max on fp32
__device__ __forceinline__ unsigned fenc(float f) {
    unsigned u = __float_as_uint(f);
    return (u & 0x80000000u) ? ~u : (u | 0x80000000u);
}
__device__ __forceinline__ float fdec(unsigned e) {
    return (e & 0x80000000u) ? __uint_as_float(e & 0x7FFFFFFFu) : __uint_as_float(~e);
}

// ============================================================================
// Kernel 1: reset min/max accumulators
// ============================================================================
__global__ void init_kernel() {
    if (threadIdx.x == 0) {
        g_xmin_e = 0xFFFFFFFFu; g_xmax_e = 0u;
        g_wmin_e = 0xFFFFFFFFu; g_wmax_e = 0u;
    }
}

// ============================================================================
// Kernel 2: per-row pass — global min/max of x and w, weight row sums
// ============================================================================
__global__ void __launch_bounds__(256) reduce_kernel(const float* __restrict__ x,
                                                     const float* __restrict__ w) {
    const int row = blockIdx.x, tid = threadIdx.x;
    const float4* xr = reinterpret_cast<const float4*>(x + ((size_t)row << 12));
    const float4* wr = reinterpret_cast<const float4*>(w + ((size_t)row << 12));
    float xmn = 3.4e38f, xmx = -3.4e38f, wmn = 3.4e38f, wmx = -3.4e38f, ws = 0.0f;
    for (int i = tid; i < 1024; i += 256) {
        float4 a = xr[i];
        xmn = fminf(xmn, fminf(fminf(a.x, a.y), fminf(a.z, a.w)));
        xmx = fmaxf(xmx, fmaxf(fmaxf(a.x, a.y), fmaxf(a.z, a.w)));
        float4 b = wr[i];
        wmn = fminf(wmn, fminf(fminf(b.x, b.y), fminf(b.z, b.w)));
        wmx = fmaxf(wmx, fmaxf(fmaxf(b.x, b.y), fmaxf(b.z, b.w)));
        ws += (b.x + b.y) + (b.z + b.w);
    }
    #pragma unroll
    for (int o = 16; o; o >>= 1) {
        xmn = fminf(xmn, __shfl_xor_sync(0xFFFFFFFFu, xmn, o));
        xmx = fmaxf(xmx, __shfl_xor_sync(0xFFFFFFFFu, xmx, o));
        wmn = fminf(wmn, __shfl_xor_sync(0xFFFFFFFFu, wmn, o));
        wmx = fmaxf(wmx, __shfl_xor_sync(0xFFFFFFFFu, wmx, o));
        ws += __shfl_xor_sync(0xFFFFFFFFu, ws, o);
    }
    __shared__ float s_xmn[8], s_xmx[8], s_wmn[8], s_wmx[8], s_ws[8];
    const int wid = tid >> 5, lane = tid & 31;
    if (lane == 0) { s_xmn[wid] = xmn; s_xmx[wid] = xmx; s_wmn[wid] = wmn; s_wmx[wid] = wmx; s_ws[wid] = ws; }
    __syncthreads();
    if (tid == 0) {
        float a = s_xmn[0], b = s_xmx[0], c = s_wmn[0], d = s_wmx[0], e = s_ws[0];
        #pragma unroll
        for (int i = 1; i < 8; i++) {
            a = fminf(a, s_xmn[i]); b = fmaxf(b, s_xmx[i]);
            c = fminf(c, s_wmn[i]); d = fmaxf(d, s_wmx[i]);
            e += s_ws[i];
        }
        atomicMin(&g_xmin_e, fenc(a)); atomicMax(&g_xmax_e, fenc(b));
        atomicMin(&g_wmin_e, fenc(c)); atomicMax(&g_wmax_e, fenc(d));
        g_rowsum[row] = e;
    }
}

// ============================================================================
// Kernel 3: scalar constants
// ============================================================================
__global__ void finalize_kernel() {
    if (threadIdx.x == 0) {
        float xmin = fdec(g_xmin_e), xmax = fdec(g_xmax_e);
        float wmin = fdec(g_wmin_e), wmax = fdec(g_wmax_e);
        float sa = (xmax - xmin) * 0.125f;  // /8 exact
        float sw = (wmax - wmin) * 0.125f;
        g_consts[0] = sa * sw;
        g_consts[1] = xmin + 4.0f * sa;
        g_consts[2] = xmin; g_consts[3] = sa;
        g_consts[4] = wmin; g_consts[5] = sw;
    }
}

// ============================================================================
// Kernel 4/5: quantize to int8 scratch. Bit-matches reference: IEEE rn div,
// clip, trunc-toward-zero (C int cast == astype(int32)).
// ============================================================================
__global__ void __launch_bounds__(256) quant_kernel(const float* __restrict__ src, int which) {
    const float zero  = which ? g_consts[4] : g_consts[2];
    const float scale = which ? g_consts[5] : g_consts[3];
    int8_t* dst = which ? g_wq8 : g_xq8;
    const size_t i = ((size_t)blockIdx.x * 256 + threadIdx.x) * 16;
    const float4* s4 = reinterpret_cast<const float4*>(src + i);
    unsigned r[4];
    #pragma unroll
    for (int k = 0; k < 4; k++) {
        float4 v = s4[k];
        float q0 = fminf(fmaxf(__fdiv_rn(v.x - zero, scale) - 4.0f, -4.0f), 3.0f);
        float q1 = fminf(fmaxf(__fdiv_rn(v.y - zero, scale) - 4.0f, -4.0f), 3.0f);
        float q2 = fminf(fmaxf(__fdiv_rn(v.z - zero, scale) - 4.0f, -4.0f), 3.0f);
        float q3 = fminf(fmaxf(__fdiv_rn(v.w - zero, scale) - 4.0f, -4.0f), 3.0f);
        r[k] = ((unsigned)((int)q0 & 0xFF))
             | ((unsigned)((int)q1 & 0xFF) << 8)
             | ((unsigned)((int)q2 & 0xFF) << 16)
             | ((unsigned)((int)q3) << 24);
    }
    *reinterpret_cast<uint4*>(dst + i) = make_uint4(r[0], r[1], r[2], r[3]);
}

// ============================================================================
// Kernel 6: s8 IMMA GEMM. 128x128x128 tile, 256 threads (2x4 warps, warp tile
// 64x32), 3-stage cp.async pipeline, XOR-swizzled SMEM + ldmatrix.x4, fused
// dequant epilogue.  D[m,n] = sum_k A[m,k]*B[n,k], both K-major int8.
// NOTE: launch_bounds(256) WITHOUT minBlocks: the former (256,2) capped regs
// at 128 and spilled the 64-reg accumulator file to local memory.
// ============================================================================
__global__ void __launch_bounds__(256) gemm_kernel(const float* __restrict__ bias,
                                                   float* __restrict__ out) {
    extern __shared__ char smem[];
    const int tid = threadIdx.x, lane = tid & 31, wid = tid >> 5;
    const int warp_m = wid >> 2, warp_n = wid & 3;   // 2 x 4 warp grid
    const int bx = blockIdx.x, by = blockIdx.y;      // bx: N tiles, by: M tiles
    const uint32_t sm0 = smem_to_u32(smem);

    const int8_t* Agbase = g_xq8 + ((size_t)(by * BM) << 12);
    const int8_t* Bgbase = g_wq8 + ((size_t)(bx * BN) << 12);

    // copy-loop coords: 1024 16B-chunks per matrix per stage; 4 per thread
    int cp_so[4], cp_go[4];
    #pragma unroll
    for (int i = 0; i < 4; i++) {
        int id = tid + i * 256;
        int r = id >> 3, c = id & 7;
        cp_so[i] = r * 128 + ((c ^ (r & 7)) << 4);  // swizzled SMEM offset
        cp_go[i] = (r << 12) + (c << 4);            // gmem byte offset
    }

    // ldmatrix lane addressing (constant xor because 16 ≡ 0 mod 8)
    const int a_row  = warp_m * 64 + (lane & 7) + ((lane >> 3) & 1) * 8;
    const int a_kbit = (lane >> 4) & 1;
    const int a_xor  = a_row & 7;
    uint32_t a_rowoff[4];
    #pragma unroll
    for (int mb = 0; mb < 4; mb++) a_rowoff[mb] = (uint32_t)(a_row + mb * 16) * 128;

    const int b_col  = warp_n * 32 + (lane & 7) + ((lane >> 4) & 1) * 8;
    const int b_kbit = (lane >> 3) & 1;
    const int b_xor  = b_col & 7;
    uint32_t b_rowoff[2];
    #pragma unroll
    for (int h = 0; h < 2; h++) b_rowoff[h] = (uint32_t)(b_col + h * 16) * 128;

    int acc[4][4][4];
    #pragma unroll
    for (int mb = 0; mb < 4; mb++)
        #pragma unroll
        for (int nb = 0; nb < 4; nb++)
            #pragma unroll
            for (int e = 0; e < 4; e++) acc[mb][nb][e] = 0;

    auto load_stage = [&](int kt, int st) {
        const uint32_t As = sm0 + st * STAGE_BYTES;
        const uint32_t Bs = As + BM * BK;
        const int8_t* Ag = Agbase + (size_t)kt * BK;
        const int8_t* Bg = Bgbase + (size_t)kt * BK;
        #pragma unroll
        for (int i = 0; i < 4; i++) {
            CP_ASYNC16(As + cp_so[i], Ag + cp_go[i]);
            CP_ASYNC16(Bs + cp_so[i], Bg + cp_go[i]);
        }
    };

    load_stage(0, 0); CP_COMMIT();
    load_stage(1, 1); CP_COMMIT();

    int st = 0, nst = 2;
    #pragma unroll 1
    for (int kt = 0; kt < NITER; kt++) {
        CP_WAIT1();
        __syncthreads();
        if (kt + 2 < NITER) load_stage(kt + 2, nst);
        CP_COMMIT();

        const uint32_t As = sm0 + st * STAGE_BYTES;
        const uint32_t Bs = As + BM * BK;
        #pragma unroll
        for (int ks = 0; ks < 4; ks++) {  // 4 x k32 steps per BK=128
            const uint32_t ac = (uint32_t)(((2 * ks + a_kbit) ^ a_xor) << 4);
            const uint32_t bc = (uint32_t)(((2 * ks + b_kbit) ^ b_xor) << 4);
            uint32_t A[4][4], Bf[2][4];
            #pragma unroll
            for (int mb = 0; mb < 4; mb++) LDSM_X4(A[mb], As + a_rowoff[mb] + ac);
            #pragma unroll
            for (int h = 0; h < 2; h++)    LDSM_X4(Bf[h], Bs + b_rowoff[h] + bc);
            #pragma unroll
            for (int mb = 0; mb < 4; mb++) {
                MMA_S8(acc[mb][0], A[mb], Bf[0][0], Bf[0][1]);
                MMA_S8(acc[mb][1], A[mb], Bf[0][2], Bf[0][3]);
                MMA_S8(acc[mb][2], A[mb], Bf[1][0], Bf[1][1]);
                MMA_S8(acc[mb][3], A[mb], Bf[1][2], Bf[1][3]);
            }
        }
        st  = (st  == 2) ? 0 : st  + 1;
        nst = (nst == 2) ? 0 : nst + 1;
    }

    // Epilogue: out[r][c] = (acc + bias[c]) * s + shc * rowsum[r]
    const float s = g_consts[0], shc = g_consts[1];
    const int gr0 = by * BM + warp_m * 64 + (lane >> 2);
    const int gc0 = bx * BN + warp_n * 32 + (lane & 3) * 2;
    #pragma unroll
    for (int mb = 0; mb < 4; mb++) {
        const int r0 = gr0 + mb * 16, r1 = r0 + 8;
        const float sh0 = shc * g_rowsum[r0];
        const float sh1 = shc * g_rowsum[r1];
        float* o0 = out + ((size_t)r0 << 12);
        float* o1 = out + ((size_t)r1 << 12);
        #pragma unroll
        for (int nb = 0; nb < 4; nb++) {
            const int gc = gc0 + nb * 8;
            const float bv0 = bias[gc], bv1 = bias[gc + 1];
            float2 v0, v1;
            v0.x = fmaf((float)acc[mb][nb][0] + bv0, s, sh0);
            v0.y = fmaf((float)acc[mb][nb][1] + bv1, s, sh0);
            v1.x = fmaf((float)acc[mb][nb][2] + bv0, s, sh1);
            v1.y = fmaf((float)acc[mb][nb][3] + bv1, s, sh1);
            *reinterpret_cast<float2*>(o0 + gc) = v0;
            *reinterpret_cast<float2*>(o1 + gc) = v1;
        }
    }
}

// ============================================================================
extern "C" void kernel_launch(void* const* d_in, const int* in_sizes, int n_in,
                              void* d_out, int out_size) {
    (void)in_sizes; (void)n_in; (void)out_size;
    const float* x    = (const float*)d_in[0];
    const float* w    = (const float*)d_in[1];
    const float* bias = (const float*)d_in[2];
    float* out = (float*)d_out;

    init_kernel<<<1, 32>>>();
    reduce_kernel<<<DIM, 256>>>(x, w);
    finalize_kernel<<<1, 32>>>();
    quant_kernel<<<DIM * DIM / (16 * 256), 256>>>(x, 0);  // 4096 blocks
    quant_kernel<<<DIM * DIM / (16 * 256), 256>>>(w, 1);

    cudaFuncSetAttribute(gemm_kernel, cudaFuncAttributeMaxDynamicSharedMemorySize, SMEM_TOTAL);
    gemm_kernel<<<dim3(DIM / BN, DIM / BM), 256, SMEM_TOTAL>>>(bias, out);
}

// round 8
// speedup vs baseline: 2.2912x; 2.2912x over previous
#include <cuda_runtime.h>
#include <cuda_fp16.h>
#include <cstdint>
#include <cstddef>

// ============================================================================
// QUIK quantized linear, B = in = out = 4096.
//   x_q = trunc(clip((x - min(x))/((max-min)/8) - 4, -4, 3))   (global affine)
//   w_q likewise; out[i,j] = (x_q[i,:]·w_q[j,:] + bias[j])*s_a*s_w
//                            + (zero_a + 4*s_a)*rowsum_w[i]    (note index i)
// R8: int8 mma.sync is EMULATED on sm_103 (measured rt≈60cyc). Switch to the
// native legacy HMMA path: f16 mma.sync m16n8k16 with f32 accum. Quantized
// values [-4,3] are f16-exact; |acc| <= 65536 is f32-exact -> still bit-exact.
// ============================================================================

#define DIM 4096
#define BM 128
#define BN 128
#define BK 64             // f16 elements per k-tile = 128 bytes per row
#define NITER (DIM / BK)  // 64
#define STAGES 3
#define STAGE_BYTES (2 * BM * 128)         // A(16K) + B(16K) = 32768
#define SMEM_TOTAL (STAGES * STAGE_BYTES)  // 98304

// ---------------- device scratch (allocation-free rule) ---------------------
__device__ unsigned g_xmin_e, g_xmax_e, g_wmin_e, g_wmax_e;
__device__ float g_rowsum[DIM];
__device__ float g_consts[8];  // 0:s=sa*sw 1:shiftc 2:x_zero 3:x_scale 4:w_zero 5:w_scale
__device__ unsigned short g_xqh[(size_t)DIM * DIM];  // f16 bits of quantized x
__device__ unsigned short g_wqh[(size_t)DIM * DIM];  // f16 bits of quantized w

// ---------------- PTX helpers (plain-sm80/75 features only) -----------------
__device__ __forceinline__ uint32_t smem_to_u32(const void* p) {
    uint32_t a;
    asm("{ .reg .u64 t; cvta.to.shared.u64 t, %1; cvt.u32.u64 %0, t; }" : "=r"(a) : "l"(p));
    return a;
}

#define CP_ASYNC16(saddr, gptr)                                              \
    asm volatile("cp.async.cg.shared.global [%0], [%1], 16;"                 \
                 :: "r"(saddr), "l"(gptr) : "memory")
#define CP_COMMIT() asm volatile("cp.async.commit_group;" ::: "memory")
#define CP_WAIT1()  asm volatile("cp.async.wait_group 1;" ::: "memory")

#define LDSM_X4(r, addr)                                                     \
    asm volatile("ldmatrix.sync.aligned.m8n8.x4.shared.b16 {%0,%1,%2,%3}, [%4];" \
                 : "=r"((r)[0]), "=r"((r)[1]), "=r"((r)[2]), "=r"((r)[3])    \
                 : "r"(addr))

// f16 HMMA, f32 accumulate: D(16x8) += A(16x16) * B(16x8)
#define MMA_F16(c, a, b0v, b1v)                                              \
    asm volatile("mma.sync.aligned.m16n8k16.row.col.f32.f16.f16.f32 "        \
                 "{%0,%1,%2,%3}, {%4,%5,%6,%7}, {%8,%9}, {%0,%1,%2,%3};"     \
                 : "+f"((c)[0]), "+f"((c)[1]), "+f"((c)[2]), "+f"((c)[3])    \
                 : "r"((a)[0]), "r"((a)[1]), "r"((a)[2]), "r"((a)[3]),       \
                   "r"(b0v), "r"(b1v))

// Monotone float<->uint encoding for atomic min/max on fp32
__device__ __forceinline__ unsigned fenc(float f) {
    unsigned u = __float_as_uint(f);
    return (u & 0x80000000u) ? ~u : (u | 0x80000000u);
}
__device__ __forceinline__ float fdec(unsigned e) {
    return (e & 0x80000000u) ? __uint_as_float(e & 0x7FFFFFFFu) : __uint_as_float(~e);
}

// ============================================================================
// Kernel 1: reset min/max accumulators
// ============================================================================
__global__ void init_kernel() {
    if (threadIdx.x == 0) {
        g_xmin_e = 0xFFFFFFFFu; g_xmax_e = 0u;
        g_wmin_e = 0xFFFFFFFFu; g_wmax_e = 0u;
    }
}

// ============================================================================
// Kernel 2: per-row pass — global min/max of x and w, weight row sums
// ============================================================================
__global__ void __launch_bounds__(256) reduce_kernel(const float* __restrict__ x,
                                                     const float* __restrict__ w) {
    const int row = blockIdx.x, tid = threadIdx.x;
    const float4* xr = reinterpret_cast<const float4*>(x + ((size_t)row << 12));
    const float4* wr = reinterpret_cast<const float4*>(w + ((size_t)row << 12));
    float xmn = 3.4e38f, xmx = -3.4e38f, wmn = 3.4e38f, wmx = -3.4e38f, ws = 0.0f;
    for (int i = tid; i < 1024; i += 256) {
        float4 a = xr[i];
        xmn = fminf(xmn, fminf(fminf(a.x, a.y), fminf(a.z, a.w)));
        xmx = fmaxf(xmx, fmaxf(fmaxf(a.x, a.y), fmaxf(a.z, a.w)));
        float4 b = wr[i];
        wmn = fminf(wmn, fminf(fminf(b.x, b.y), fminf(b.z, b.w)));
        wmx = fmaxf(wmx, fmaxf(fmaxf(b.x, b.y), fmaxf(b.z, b.w)));
        ws += (b.x + b.y) + (b.z + b.w);
    }
    #pragma unroll
    for (int o = 16; o; o >>= 1) {
        xmn = fminf(xmn, __shfl_xor_sync(0xFFFFFFFFu, xmn, o));
        xmx = fmaxf(xmx, __shfl_xor_sync(0xFFFFFFFFu, xmx, o));
        wmn = fminf(wmn, __shfl_xor_sync(0xFFFFFFFFu, wmn, o));
        wmx = fmaxf(wmx, __shfl_xor_sync(0xFFFFFFFFu, wmx, o));
        ws += __shfl_xor_sync(0xFFFFFFFFu, ws, o);
    }
    __shared__ float s_xmn[8], s_xmx[8], s_wmn[8], s_wmx[8], s_ws[8];
    const int wid = tid >> 5, lane = tid & 31;
    if (lane == 0) { s_xmn[wid] = xmn; s_xmx[wid] = xmx; s_wmn[wid] = wmn; s_wmx[wid] = wmx; s_ws[wid] = ws; }
    __syncthreads();
    if (tid == 0) {
        float a = s_xmn[0], b = s_xmx[0], c = s_wmn[0], d = s_wmx[0], e = s_ws[0];
        #pragma unroll
        for (int i = 1; i < 8; i++) {
            a = fminf(a, s_xmn[i]); b = fmaxf(b, s_xmx[i]);
            c = fminf(c, s_wmn[i]); d = fmaxf(d, s_wmx[i]);
            e += s_ws[i];
        }
        atomicMin(&g_xmin_e, fenc(a)); atomicMax(&g_xmax_e, fenc(b));
        atomicMin(&g_wmin_e, fenc(c)); atomicMax(&g_wmax_e, fenc(d));
        g_rowsum[row] = e;
    }
}

// ============================================================================
// Kernel 3: scalar constants
// ============================================================================
__global__ void finalize_kernel() {
    if (threadIdx.x == 0) {
        float xmin = fdec(g_xmin_e), xmax = fdec(g_xmax_e);
        float wmin = fdec(g_wmin_e), wmax = fdec(g_wmax_e);
        float sa = (xmax - xmin) * 0.125f;  // /8 exact
        float sw = (wmax - wmin) * 0.125f;
        g_consts[0] = sa * sw;
        g_consts[1] = xmin + 4.0f * sa;
        g_consts[2] = xmin; g_consts[3] = sa;
        g_consts[4] = wmin; g_consts[5] = sw;
    }
}

// ============================================================================
// Kernel 4/5: quantize to f16 scratch. Bit-matches reference: IEEE rn div,
// clip, trunc-toward-zero; small ints are exact in f16.
// ============================================================================
__global__ void __launch_bounds__(256) quant_kernel(const float* __restrict__ src, int which) {
    const float zero  = which ? g_consts[4] : g_consts[2];
    const float scale = which ? g_consts[5] : g_consts[3];
    unsigned short* dst = which ? g_wqh : g_xqh;
    const size_t i = ((size_t)blockIdx.x * 256 + threadIdx.x) * 8;
    const float4* s4 = reinterpret_cast<const float4*>(src + i);
    float4 a = s4[0], b = s4[1];
    float v[8] = {a.x, a.y, a.z, a.w, b.x, b.y, b.z, b.w};
    unsigned r[4];
    #pragma unroll
    for (int k = 0; k < 4; k++) {
        float q0 = fminf(fmaxf(__fdiv_rn(v[2 * k] - zero, scale) - 4.0f, -4.0f), 3.0f);
        float q1 = fminf(fmaxf(__fdiv_rn(v[2 * k + 1] - zero, scale) - 4.0f, -4.0f), 3.0f);
        unsigned lo = __half_as_ushort(__float2half_rn((float)(int)q0));
        unsigned hi = __half_as_ushort(__float2half_rn((float)(int)q1));
        r[k] = lo | (hi << 16);
    }
    *reinterpret_cast<uint4*>(dst + i) = make_uint4(r[0], r[1], r[2], r[3]);
}

// ============================================================================
// Kernel 6: f16 HMMA GEMM. 128x128 tile, BK=64 (128B rows -> same swizzle as
// before), 256 threads (2x4 warps, warp tile 64x32), 3-stage cp.async
// pipeline, ldmatrix.x4, fused dequant epilogue.
// D[m,n] = sum_k A[m,k]*B[n,k], both K-major f16.
// ============================================================================
__global__ void __launch_bounds__(256) gemm_kernel(const float* __restrict__ bias,
                                                   float* __restrict__ out) {
    extern __shared__ char smem[];
    const int tid = threadIdx.x, lane = tid & 31, wid = tid >> 5;
    const int warp_m = wid >> 2, warp_n = wid & 3;   // 2 x 4 warp grid
    const int bx = blockIdx.x, by = blockIdx.y;      // bx: N tiles, by: M tiles
    const uint32_t sm0 = smem_to_u32(smem);

    const unsigned short* Agbase = g_xqh + ((size_t)(by * BM) << 12);
    const unsigned short* Bgbase = g_wqh + ((size_t)(bx * BN) << 12);

    // copy-loop coords: 1024 16B-chunks per matrix per stage; 4 per thread
    // (row = one 128B tile row = 64 f16; gmem row stride = 4096 f16 = 8192B)
    int cp_so[4], cp_go[4];
    #pragma unroll
    for (int i = 0; i < 4; i++) {
        int id = tid + i * 256;
        int r = id >> 3, c = id & 7;
        cp_so[i] = r * 128 + ((c ^ (r & 7)) << 4);  // swizzled SMEM offset
        cp_go[i] = (r << 13) + (c << 4);            // gmem byte offset
    }

    // ldmatrix lane addressing: row = (lane&7) + bit3*8, k16-chunk half = bit4
    const int a_row  = warp_m * 64 + (lane & 7) + ((lane >> 3) & 1) * 8;
    const int a_kbit = (lane >> 4) & 1;
    const int a_xor  = a_row & 7;
    uint32_t a_rowoff[4];
    #pragma unroll
    for (int mb = 0; mb < 4; mb++) a_rowoff[mb] = (uint32_t)(a_row + mb * 16) * 128;

    const int b_col  = warp_n * 32 + (lane & 7) + ((lane >> 3) & 1) * 8;
    const int b_kbit = (lane >> 4) & 1;
    const int b_xor  = b_col & 7;
    uint32_t b_rowoff[2];
    #pragma unroll
    for (int h = 0; h < 2; h++) b_rowoff[h] = (uint32_t)(b_col + h * 16) * 128;

    float acc[4][4][4];
    #pragma unroll
    for (int mb = 0; mb < 4; mb++)
        #pragma unroll
        for (int nb = 0; nb < 4; nb++)
            #pragma unroll
            for (int e = 0; e < 4; e++) acc[mb][nb][e] = 0.0f;

    auto load_stage = [&](int kt, int st) {
        const uint32_t As = sm0 + st * STAGE_BYTES;
        const uint32_t Bs = As + BM * 128;
        const unsigned short* Ag = Agbase + (size_t)kt * BK;
        const unsigned short* Bg = Bgbase + (size_t)kt * BK;
        #pragma unroll
        for (int i = 0; i < 4; i++) {
            CP_ASYNC16(As + cp_so[i], Ag + (cp_go[i] >> 1));
            CP_ASYNC16(Bs + cp_so[i], Bg + (cp_go[i] >> 1));
        }
    };

    load_stage(0, 0); CP_COMMIT();
    load_stage(1, 1); CP_COMMIT();

    int st = 0, nst = 2;
    #pragma unroll 1
    for (int kt = 0; kt < NITER; kt++) {
        CP_WAIT1();
        __syncthreads();
        if (kt + 2 < NITER) load_stage(kt + 2, nst);
        CP_COMMIT();

        const uint32_t As = sm0 + st * STAGE_BYTES;
        const uint32_t Bs = As + BM * 128;
        #pragma unroll
        for (int ks = 0; ks < 4; ks++) {  // 4 x k16 steps per BK=64
            const uint32_t ac = (uint32_t)(((2 * ks + a_kbit) ^ a_xor) << 4);
            const uint32_t bc = (uint32_t)(((2 * ks + b_kbit) ^ b_xor) << 4);
            uint32_t A[4][4], Bf[2][4];
            #pragma unroll
            for (int mb = 0; mb < 4; mb++) LDSM_X4(A[mb], As + a_rowoff[mb] + ac);
            #pragma unroll
            for (int h = 0; h < 2; h++)    LDSM_X4(Bf[h], Bs + b_rowoff[h] + bc);
            // Bf[h] matrices: m0=(n0-7,klo) m1=(n8-15,klo) m2=(n0-7,khi) m3=(n8-15,khi)
            #pragma unroll
            for (int mb = 0; mb < 4; mb++) {
                MMA_F16(acc[mb][0], A[mb], Bf[0][0], Bf[0][2]);
                MMA_F16(acc[mb][1], A[mb], Bf[0][1], Bf[0][3]);
                MMA_F16(acc[mb][2], A[mb], Bf[1][0], Bf[1][2]);
                MMA_F16(acc[mb][3], A[mb], Bf[1][1], Bf[1][3]);
            }
        }
        st  = (st  == 2) ? 0 : st  + 1;
        nst = (nst == 2) ? 0 : nst + 1;
    }

    // Epilogue: out[r][c] = (acc + bias[c]) * s + shc * rowsum[r]
    const float s = g_consts[0], shc = g_consts[1];
    const int gr0 = by * BM + warp_m * 64 + (lane >> 2);
    const int gc0 = bx * BN + warp_n * 32 + (lane & 3) * 2;
    #pragma unroll
    for (int mb = 0; mb < 4; mb++) {
        const int r0 = gr0 + mb * 16, r1 = r0 + 8;
        const float sh0 = shc * g_rowsum[r0];
        const float sh1 = shc * g_rowsum[r1];
        float* o0 = out + ((size_t)r0 << 12);
        float* o1 = out + ((size_t)r1 << 12);
        #pragma unroll
        for (int nb = 0; nb < 4; nb++) {
            const int gc = gc0 + nb * 8;
            const float bv0 = bias[gc], bv1 = bias[gc + 1];
            float2 v0, v1;
            v0.x = fmaf(acc[mb][nb][0] + bv0, s, sh0);
            v0.y = fmaf(acc[mb][nb][1] + bv1, s, sh0);
            v1.x = fmaf(acc[mb][nb][2] + bv0, s, sh1);
            v1.y = fmaf(acc[mb][nb][3] + bv1, s, sh1);
            *reinterpret_cast<float2*>(o0 + gc) = v0;
            *reinterpret_cast<float2*>(o1 + gc) = v1;
        }
    }
}

// ============================================================================
extern "C" void kernel_launch(void* const* d_in, const int* in_sizes, int n_in,
                              void* d_out, int out_size) {
    (void)in_sizes; (void)n_in; (void)out_size;
    const float* x    = (const float*)d_in[0];
    const float* w    = (const float*)d_in[1];
    const float* bias = (const float*)d_in[2];
    float* out = (float*)d_out;

    init_kernel<<<1, 32>>>();
    reduce_kernel<<<DIM, 256>>>(x, w);
    finalize_kernel<<<1, 32>>>();
    quant_kernel<<<DIM * DIM / (8 * 256), 256>>>(x, 0);  // 8192 blocks
    quant_kernel<<<DIM * DIM / (8 * 256), 256>>>(w, 1);

    cudaFuncSetAttribute(gemm_kernel, cudaFuncAttributeMaxDynamicSharedMemorySize, SMEM_TOTAL);
    gemm_kernel<<<dim3(DIM / BN, DIM / BM), 256, SMEM_TOTAL>>>(bias, out);
}